// round 2
// baseline (speedup 1.0000x reference)
#include <cuda_runtime.h>
#include <cuda_bf16.h>

// IntraAgg: segment-mean neighbor aggregation.
// inputs (metadata order):
//   d_in[0] features    float32 [100000*256]
//   d_in[1] neigh_idx   int32   [524288]   (JAX x64 disabled -> int32)
//   d_in[2] segment_ids int32   [524288]   (sorted ascending)
//   d_in[3] self_feats  float32 [16384*256]
// output: float32 [16384*512] = concat(self - agg, agg)

#define D_FEAT 256
#define VEC    4                 // float4 per thread
#define TPB    (D_FEAT / VEC)    // 64 threads

__global__ __launch_bounds__(TPB) void intra_agg_kernel(
    const float* __restrict__ features,
    const int* __restrict__ neigh_idx,
    const int* __restrict__ seg_ids,
    const float* __restrict__ self_feats,
    float* __restrict__ out,
    int n_edges)
{
    const int b = blockIdx.x;
    const int tid = threadIdx.x;

    // Binary search [start, end) such that seg_ids[e] == b.
    // All threads compute identically (broadcast loads) — cheap & uniform.
    int lo = 0, hi = n_edges;
    while (lo < hi) {
        int m = (lo + hi) >> 1;
        if (__ldg(seg_ids + m) < b) lo = m + 1; else hi = m;
    }
    const int start = lo;
    hi = n_edges;
    while (lo < hi) {
        int m = (lo + hi) >> 1;
        if (__ldg(seg_ids + m) <= b) lo = m + 1; else hi = m;
    }
    const int end = lo;

    float4 acc0 = make_float4(0.f, 0.f, 0.f, 0.f);
    float4 acc1 = make_float4(0.f, 0.f, 0.f, 0.f);

    int e = start;
    // unroll-by-2: two independent gather chains for MLP
    for (; e + 1 < end; e += 2) {
        const int n0 = __ldg(neigh_idx + e);
        const int n1 = __ldg(neigh_idx + e + 1);
        const float4 f0 = __ldg(reinterpret_cast<const float4*>(features + (size_t)n0 * D_FEAT) + tid);
        const float4 f1 = __ldg(reinterpret_cast<const float4*>(features + (size_t)n1 * D_FEAT) + tid);
        acc0.x += f0.x; acc0.y += f0.y; acc0.z += f0.z; acc0.w += f0.w;
        acc1.x += f1.x; acc1.y += f1.y; acc1.z += f1.z; acc1.w += f1.w;
    }
    if (e < end) {
        const int n0 = __ldg(neigh_idx + e);
        const float4 f0 = __ldg(reinterpret_cast<const float4*>(features + (size_t)n0 * D_FEAT) + tid);
        acc0.x += f0.x; acc0.y += f0.y; acc0.z += f0.z; acc0.w += f0.w;
    }

    float4 agg;
    const float inv = 1.0f / fmaxf((float)(end - start), 1.0f);
    agg.x = (acc0.x + acc1.x) * inv;
    agg.y = (acc0.y + acc1.y) * inv;
    agg.z = (acc0.z + acc1.z) * inv;
    agg.w = (acc0.w + acc1.w) * inv;

    const float4 s = __ldg(reinterpret_cast<const float4*>(self_feats + (size_t)b * D_FEAT) + tid);
    float4 diff;
    diff.x = s.x - agg.x; diff.y = s.y - agg.y;
    diff.z = s.z - agg.z; diff.w = s.w - agg.w;

    float* orow = out + (size_t)b * (2 * D_FEAT);
    reinterpret_cast<float4*>(orow)[tid] = diff;
    reinterpret_cast<float4*>(orow + D_FEAT)[tid] = agg;
}

extern "C" void kernel_launch(void* const* d_in, const int* in_sizes, int n_in,
                              void* d_out, int out_size)
{
    const float* features   = (const float*)d_in[0];
    const int*   neigh_idx  = (const int*)d_in[1];
    const int*   seg_ids    = (const int*)d_in[2];
    const float* self_feats = (const float*)d_in[3];
    float*       out        = (float*)d_out;

    const int n_edges = in_sizes[1];
    const int n_batch = in_sizes[3] / D_FEAT;   // 16384

    intra_agg_kernel<<<n_batch, TPB>>>(features, neigh_idx, seg_ids,
                                       self_feats, out, n_edges);
}